// round 14
// baseline (speedup 1.0000x reference)
#include <cuda_runtime.h>
#include <cuda_fp16.h>
#include <cstdint>

// ---------------------------------------------------------------------------
// Problem constants
// ---------------------------------------------------------------------------
#define NB   4
#define CIN  256
#define CKEY 448
#define NTOK 4096
#define NEGV (-1e15f)
#define EPSV 1e-5f
#define CKP  512   // padded CKEY for projection N-dim

// ---------------------------------------------------------------------------
// Scratch (static device globals; no runtime allocation)
// ---------------------------------------------------------------------------
__device__ __half g_ckT [(size_t)NB * NTOK * CKEY];   // [b][N][Ck] ckey^T
__device__ __half g_skT [(size_t)NB * NTOK * CKEY];   // [b][N][Ck] skey^T
__device__ __half g_stT [(size_t)NB * NTOK * CIN];    // [b][N][C]  style^T
__device__ __half g_FqN [(size_t)NB * NTOK * CKEY];   // [b][N][Ck] f(ckey)
__device__ __half g_GN  [(size_t)NB * NTOK * CKEY];   // [b][N][Ck] g(skey)
__device__ __half g_HvT [(size_t)NB * CIN  * NTOK];   // [b][C][N]  h(style)
__device__ __half g_Hv2T[(size_t)NB * CIN  * NTOK];   // [b][C][N]  h(style)^2
__device__ float  g_S   [(size_t)NB * NTOK * NTOK];   // [b][N][N]  scores (fp32)
__device__ __half g_A   [(size_t)NB * NTOK * NTOK];   // [b][N][N]  attn (half)
__device__ float  g_meanT[(size_t)NB * CIN * NTOK];   // [b][C][N]
__device__ float  g_m2T [(size_t)NB * CIN  * NTOK];   // [b][C][N]
__device__ __half g_Wf  [CKP * CKEY];                 // rounded, zero-padded rows
__device__ __half g_Wg  [CKP * CKEY];
__device__ __half g_Wh  [CIN * CIN];
__device__ float  g_bf  [CKP];
__device__ float  g_bg  [CKP];
__device__ float  g_cmean[NB * CIN];
__device__ float  g_crstd[NB * CIN];

// ---------------------------------------------------------------------------
// Helpers
// ---------------------------------------------------------------------------
__device__ __forceinline__ uint32_t smem_u32(const void* p) {
    uint32_t a;
    asm("{ .reg .u64 t; cvta.to.shared.u64 t, %1; cvt.u32.u64 %0, t; }"
        : "=r"(a) : "l"(p));
    return a;
}
__device__ __forceinline__ void cp16(uint32_t s, const void* g) {
    asm volatile("cp.async.cg.shared.global [%0], [%1], 16;" :: "r"(s), "l"(g));
}
__device__ __forceinline__ void cp_commit() {
    asm volatile("cp.async.commit_group;" ::: "memory");
}
template <int N> __device__ __forceinline__ void cp_wait() {
    asm volatile("cp.async.wait_group %0;" :: "n"(N) : "memory");
}
__device__ __forceinline__ void mma_f16(float* d, const uint32_t* a, const uint32_t* b) {
    asm volatile(
        "mma.sync.aligned.m16n8k16.row.col.f32.f16.f16.f32 "
        "{%0,%1,%2,%3}, {%4,%5,%6,%7}, {%8,%9}, {%0,%1,%2,%3};"
        : "+f"(d[0]), "+f"(d[1]), "+f"(d[2]), "+f"(d[3])
        : "r"(a[0]), "r"(a[1]), "r"(a[2]), "r"(a[3]), "r"(b[0]), "r"(b[1]));
}
__device__ __forceinline__ void ldsm_x4(uint32_t* r, uint32_t a) {
    asm volatile("ldmatrix.sync.aligned.m8n8.x4.shared.b16 {%0,%1,%2,%3}, [%4];"
        : "=r"(r[0]), "=r"(r[1]), "=r"(r[2]), "=r"(r[3]) : "r"(a));
}
__device__ __forceinline__ void ldsm_x2(uint32_t* r, uint32_t a) {
    asm volatile("ldmatrix.sync.aligned.m8n8.x2.shared.b16 {%0,%1}, [%2];"
        : "=r"(r[0]), "=r"(r[1]) : "r"(a));
}

// BK = 64 halves per k-block. smem row stride: 72 halves (144 B).
// LDSM conflict check: chunk index (r*144/16) mod 8 = 9r mod 8 -> 8 distinct.
#define SRS 72
#define NSTG 3   // pipeline stages

// ---------------------------------------------------------------------------
// Generic FP16 mma.sync GEMM:  C[M][N] = A[M][K] * B[N][K]^T   (fp32 accum)
//   256 threads / 2 CTAs per SM, BK=64 halves, 3-stage cp.async pipeline
//   with ONE __syncthreads per iteration, ldmatrix fragment loads.
//   Warp grid WMW x (8/WMW); warp tile (BM/WMW) x (BN*WMW/8).
//   BIAS_MODE: 0 none, 1 along M, 2 along N (bias fp32)
//   SQ: also write C2 = rn(h*h), h = rn(C)  (CT == __half)
//   CT: output type (float or __half). Store guard: col < Nrt.
//   K must be a multiple of 64.
// ---------------------------------------------------------------------------
template <int BM, int BN, int WMW, int BIAS_MODE, bool SQ, typename CT>
__global__ __launch_bounds__(256, 2) void mma_gemmH(
    const __half* __restrict__ A, const __half* __restrict__ B,
    const float* __restrict__ bias,
    CT* __restrict__ C, CT* __restrict__ C2,
    int Nrt, int K, int lda, int ldb, int ldc,
    size_t sA, size_t sB, size_t sC)
{
    constexpr int WNW = 8 / WMW;
    constexpr int WTM = BM / WMW;
    constexpr int WTN = BN / WNW;
    constexpr int MI  = WTM / 16;
    constexpr int NI  = WTN / 8;
    constexpr int ASZ = BM * SRS;          // halves
    constexpr int BSZ = BN * SRS;
    constexpr int STG = ASZ + BSZ;
    constexpr int ACH = BM * 8 / 256;      // cp16 chunks per thread (A), 8 per row
    constexpr int BCH = BN * 8 / 256;

    extern __shared__ __half smh[];
    const uint32_t sbase = smem_u32(smh);

    const int tid = threadIdx.x, lane = tid & 31, wid = tid >> 5;
    const int wM = wid % WMW, wN = wid / WMW;
    const int m0 = blockIdx.y * BM, n0 = blockIdx.x * BN, b = blockIdx.z;

    A += (size_t)b * sA + (size_t)m0 * lda;
    B += (size_t)b * sB + (size_t)n0 * ldb;
    C += (size_t)b * sC;
    if (SQ) C2 += (size_t)b * sC;

    float acc[MI][NI][4];
#pragma unroll
    for (int mi = 0; mi < MI; mi++)
#pragma unroll
        for (int ni = 0; ni < NI; ni++)
#pragma unroll
            for (int q = 0; q < 4; q++) acc[mi][ni][q] = 0.f;

    const int NK = K >> 6;   // 64 halves per k-block

    // prefetch stages 0 and 1
#pragma unroll
    for (int p = 0; p < 2; p++) {
        if (p < NK) {
            const uint32_t sb = sbase + (uint32_t)(p * STG) * 2;
            const int k0 = p << 6;
#pragma unroll
            for (int v = 0; v < ACH; v++) {
                int t = tid + v * 256, r = t >> 3, ch = t & 7;
                cp16(sb + (uint32_t)(r * SRS + ch * 8) * 2, A + (size_t)r * lda + k0 + ch * 8);
            }
#pragma unroll
            for (int v = 0; v < BCH; v++) {
                int t = tid + v * 256, r = t >> 3, ch = t & 7;
                cp16(sb + (uint32_t)(ASZ + r * SRS + ch * 8) * 2, B + (size_t)r * ldb + k0 + ch * 8);
            }
        }
        cp_commit();
    }

    const int g = lane >> 2, tq = lane & 3;
    // ldmatrix per-lane offsets (bytes)
    const uint32_t aoff = (uint32_t)((lane & 15) * SRS + (lane >> 4) * 8) * 2;
    const uint32_t boff = (uint32_t)((lane & 7) * SRS + ((lane >> 3) & 1) * 8) * 2;

    int stg = 0, pstg = 2;
    for (int i = 0; i < NK; i++) {
        cp_wait<1>();
        __syncthreads();

        if (i + 2 < NK) {
            const uint32_t sb = sbase + (uint32_t)(pstg * STG) * 2;
            const int k0 = (i + 2) << 6;
#pragma unroll
            for (int v = 0; v < ACH; v++) {
                int t = tid + v * 256, r = t >> 3, ch = t & 7;
                cp16(sb + (uint32_t)(r * SRS + ch * 8) * 2, A + (size_t)r * lda + k0 + ch * 8);
            }
#pragma unroll
            for (int v = 0; v < BCH; v++) {
                int t = tid + v * 256, r = t >> 3, ch = t & 7;
                cp16(sb + (uint32_t)(ASZ + r * SRS + ch * 8) * 2, B + (size_t)r * ldb + k0 + ch * 8);
            }
        }
        cp_commit();
        if (++pstg == NSTG) pstg = 0;

        const uint32_t stg_b = sbase + (uint32_t)(stg * STG) * 2;
        const uint32_t bstg_b = stg_b + (uint32_t)ASZ * 2;

#pragma unroll
        for (int kk = 0; kk < 4; kk++) {
            const uint32_t kh = kk * 16 * 2;   // byte offset within row
            uint32_t af[MI][4], bf[NI][2];
#pragma unroll
            for (int mi = 0; mi < MI; mi++)
                ldsm_x4(af[mi], stg_b + (uint32_t)((wM * WTM + mi * 16) * SRS) * 2 + kh + aoff);
#pragma unroll
            for (int ni = 0; ni < NI; ni++)
                ldsm_x2(bf[ni], bstg_b + (uint32_t)((wN * WTN + ni * 8) * SRS) * 2 + kh + boff);
#pragma unroll
            for (int mi = 0; mi < MI; mi++)
#pragma unroll
                for (int ni = 0; ni < NI; ni++)
                    mma_f16(acc[mi][ni], af[mi], bf[ni]);
        }
        if (++stg == NSTG) stg = 0;
    }

    // ---- epilogue ----
#pragma unroll
    for (int mi = 0; mi < MI; mi++) {
        const int row0 = m0 + wM * WTM + mi * 16 + g;
        float bm0 = 0.f, bm1 = 0.f;
        if (BIAS_MODE == 1) { bm0 = bias[row0]; bm1 = bias[row0 + 8]; }
#pragma unroll
        for (int ni = 0; ni < NI; ni++) {
            const int col = n0 + wN * WTN + ni * 8 + tq * 2;
            if (col >= Nrt) continue;
            float o0 = acc[mi][ni][0], o1 = acc[mi][ni][1];
            float o2 = acc[mi][ni][2], o3 = acc[mi][ni][3];
            if (BIAS_MODE == 1) { o0 += bm0; o1 += bm0; o2 += bm1; o3 += bm1; }
            if (BIAS_MODE == 2) {
                float bn0 = bias[col], bn1 = bias[col + 1];
                o0 += bn0; o1 += bn1; o2 += bn0; o3 += bn1;
            }
            if (sizeof(CT) == 4) {
                float* Cf = reinterpret_cast<float*>(C);
                *reinterpret_cast<float2*>(&Cf[(size_t)row0 * ldc + col])       = make_float2(o0, o1);
                *reinterpret_cast<float2*>(&Cf[(size_t)(row0 + 8) * ldc + col]) = make_float2(o2, o3);
            } else {
                __half* Ch = reinterpret_cast<__half*>(C);
                __half h0 = __float2half_rn(o0), h1 = __float2half_rn(o1);
                __half h2 = __float2half_rn(o2), h3 = __float2half_rn(o3);
                *reinterpret_cast<__half2*>(&Ch[(size_t)row0 * ldc + col])       = __halves2half2(h0, h1);
                *reinterpret_cast<__half2*>(&Ch[(size_t)(row0 + 8) * ldc + col]) = __halves2half2(h2, h3);
                if (SQ) {
                    __half* C2h = reinterpret_cast<__half*>(C2);
                    float f0 = __half2float(h0), f1 = __half2float(h1);
                    float f2 = __half2float(h2), f3 = __half2float(h3);
                    __half q0 = __float2half_rn(f0 * f0), q1 = __float2half_rn(f1 * f1);
                    __half q2 = __float2half_rn(f2 * f2), q3 = __float2half_rn(f3 * f3);
                    *reinterpret_cast<__half2*>(&C2h[(size_t)row0 * ldc + col])       = __halves2half2(q0, q1);
                    *reinterpret_cast<__half2*>(&C2h[(size_t)(row0 + 8) * ldc + col]) = __halves2half2(q2, q3);
                }
            }
        }
    }
}

// ---------------------------------------------------------------------------
// Dual-B fused FP16 GEMM for mean & m2 (shares attn A tiles), BK=64, 3-stage:
//   C1[n][c] = A[n][:] . B1[c][:],  C2[n][c] = A[n][:] . B2[c][:]
//   BM=128 (tokens), BN=64 (channels), warps 4x2 -> warp tile 32x32.
//   2 CTAs/SM. fp32 accumulate.
//   Epilogue: smem-staged transpose -> coalesced float4 stores of out[c][n].
// ---------------------------------------------------------------------------
#define DUAL_SMEM ((128 * SRS + 2 * 64 * SRS) * 2 * NSTG)
#define TPD 132   // transpose tile row stride (floats)
__global__ __launch_bounds__(256, 2) void mma_gemm_dualH(
    const __half* __restrict__ A, const __half* __restrict__ B1,
    const __half* __restrict__ B2,
    float* __restrict__ C1, float* __restrict__ C2)
{
    constexpr int BM = 128, BN = 64;
    constexpr int ASZ = BM * SRS, BSZ = BN * SRS;
    constexpr int STG = ASZ + 2 * BSZ;

    extern __shared__ __half smh[];
    const uint32_t sbase = smem_u32(smh);

    const int tid = threadIdx.x, lane = tid & 31, wid = tid >> 5;
    const int wM = wid & 3, wN = wid >> 2;
    const int m0 = blockIdx.y * BM, n0 = blockIdx.x * BN, b = blockIdx.z;

    A  += (size_t)b * NTOK * NTOK + (size_t)m0 * NTOK;
    B1 += (size_t)b * CIN * NTOK + (size_t)n0 * NTOK;
    B2 += (size_t)b * CIN * NTOK + (size_t)n0 * NTOK;
    C1 += (size_t)b * CIN * NTOK;
    C2 += (size_t)b * CIN * NTOK;

    float acc1[2][4][4], acc2[2][4][4];
#pragma unroll
    for (int mi = 0; mi < 2; mi++)
#pragma unroll
        for (int ni = 0; ni < 4; ni++)
#pragma unroll
            for (int q = 0; q < 4; q++) { acc1[mi][ni][q] = 0.f; acc2[mi][ni][q] = 0.f; }

    const int NK = NTOK >> 6;   // 64

    // prefetch stages 0, 1
#pragma unroll
    for (int p = 0; p < 2; p++) {
        const uint32_t sb = sbase + (uint32_t)(p * STG) * 2;
        const int k0 = p << 6;
#pragma unroll
        for (int v = 0; v < 4; v++) {
            int t = tid + v * 256, r = t >> 3, ch = t & 7;
            cp16(sb + (uint32_t)(r * SRS + ch * 8) * 2, A + (size_t)r * NTOK + k0 + ch * 8);
        }
#pragma unroll
        for (int v = 0; v < 2; v++) {
            int t = tid + v * 256, r = t >> 3, ch = t & 7;
            cp16(sb + (uint32_t)(ASZ + r * SRS + ch * 8) * 2, B1 + (size_t)r * NTOK + k0 + ch * 8);
            cp16(sb + (uint32_t)(ASZ + BSZ + r * SRS + ch * 8) * 2, B2 + (size_t)r * NTOK + k0 + ch * 8);
        }
        cp_commit();
    }

    const int g = lane >> 2, tq = lane & 3;
    const uint32_t aoff = (uint32_t)((lane & 15) * SRS + (lane >> 4) * 8) * 2;
    const uint32_t boff = (uint32_t)((lane & 7) * SRS + ((lane >> 3) & 1) * 8) * 2;

    int stg = 0, pstg = 2;
    for (int i = 0; i < NK; i++) {
        cp_wait<1>();
        __syncthreads();

        if (i + 2 < NK) {
            const uint32_t sb = sbase + (uint32_t)(pstg * STG) * 2;
            const int k0 = (i + 2) << 6;
#pragma unroll
            for (int v = 0; v < 4; v++) {
                int t = tid + v * 256, r = t >> 3, ch = t & 7;
                cp16(sb + (uint32_t)(r * SRS + ch * 8) * 2, A + (size_t)r * NTOK + k0 + ch * 8);
            }
#pragma unroll
            for (int v = 0; v < 2; v++) {
                int t = tid + v * 256, r = t >> 3, ch = t & 7;
                cp16(sb + (uint32_t)(ASZ + r * SRS + ch * 8) * 2, B1 + (size_t)r * NTOK + k0 + ch * 8);
                cp16(sb + (uint32_t)(ASZ + BSZ + r * SRS + ch * 8) * 2, B2 + (size_t)r * NTOK + k0 + ch * 8);
            }
        }
        cp_commit();
        if (++pstg == NSTG) pstg = 0;

        const uint32_t stg_b = sbase + (uint32_t)(stg * STG) * 2;
        const uint32_t b1stg = stg_b + (uint32_t)ASZ * 2;
        const uint32_t b2stg = b1stg + (uint32_t)BSZ * 2;

#pragma unroll
        for (int kk = 0; kk < 4; kk++) {
            const uint32_t kh = kk * 16 * 2;
            uint32_t af[2][4], bf1[4][2], bf2[4][2];
#pragma unroll
            for (int mi = 0; mi < 2; mi++)
                ldsm_x4(af[mi], stg_b + (uint32_t)((wM * 32 + mi * 16) * SRS) * 2 + kh + aoff);
#pragma unroll
            for (int ni = 0; ni < 4; ni++) {
                ldsm_x2(bf1[ni], b1stg + (uint32_t)((wN * 32 + ni * 8) * SRS) * 2 + kh + boff);
                ldsm_x2(bf2[ni], b2stg + (uint32_t)((wN * 32 + ni * 8) * SRS) * 2 + kh + boff);
            }
#pragma unroll
            for (int mi = 0; mi < 2; mi++)
#pragma unroll
                for (int ni = 0; ni < 4; ni++) {
                    mma_f16(acc1[mi][ni], af[mi], bf1[ni]);
                    mma_f16(acc2[mi][ni], af[mi], bf2[ni]);
                }
        }
        if (++stg == NSTG) stg = 0;
    }

    // ---- epilogue: smem transpose -> coalesced float4 row stores ----
    __syncthreads();   // mainloop smem dead; safe to reuse
    float* smt = reinterpret_cast<float*>(smh);   // [BN][TPD]

#pragma unroll
    for (int pass = 0; pass < 2; pass++) {
        float (*acc)[4][4] = (pass == 0) ? acc1 : acc2;
        float* Cout = (pass == 0) ? C1 : C2;
#pragma unroll
        for (int mi = 0; mi < 2; mi++) {
            const int row = wM * 32 + mi * 16 + g;      // local token row
#pragma unroll
            for (int ni = 0; ni < 4; ni++) {
                const int col = wN * 32 + ni * 8 + tq * 2;  // local channel
                smt[col * TPD + row]           = acc[mi][ni][0];
                smt[(col + 1) * TPD + row]     = acc[mi][ni][1];
                smt[col * TPD + row + 8]       = acc[mi][ni][2];
                smt[(col + 1) * TPD + row + 8] = acc[mi][ni][3];
            }
        }
        __syncthreads();
#pragma unroll
        for (int v = 0; v < 8; v++) {
            int idx = tid + v * 256;        // 2048 float4 chunks
            int col = idx >> 5, ch = idx & 31;
            float4 val = *reinterpret_cast<float4*>(&smt[col * TPD + ch * 4]);
            *reinterpret_cast<float4*>(&Cout[(size_t)(n0 + col) * NTOK + m0 + ch * 4]) = val;
        }
        __syncthreads();
    }
}

// ---------------------------------------------------------------------------
// Weight prep: round W to half, pad rows to dstRows with zeros; pad bias (f32).
// ---------------------------------------------------------------------------
__global__ void prep_w_kernel(const float* __restrict__ W, const float* __restrict__ bias,
                              __half* __restrict__ Wd, float* __restrict__ bd,
                              int rows, int cols, int dstRows)
{
    int i = blockIdx.x * 256 + threadIdx.x;
    int total = dstRows * cols;
    if (i < total) {
        int r = i / cols;
        Wd[i] = (r < rows) ? __float2half_rn(W[i]) : __float2half_rn(0.f);
    }
    if (bd && i < dstRows) bd[i] = (i < rows) ? bias[i] : 0.f;
}

// ---------------------------------------------------------------------------
// Transpose [C][N] fp32 -> [N][C] half. Two tensors via z split.
// ---------------------------------------------------------------------------
template <int C>
__global__ __launch_bounds__(256) void transpose_in_kernel(
    const float* __restrict__ in0, __half* __restrict__ out0,
    const float* __restrict__ in1, __half* __restrict__ out1)
{
    __shared__ float t[32][33];
    const int z = blockIdx.z;
    const int b = z & (NB - 1);
    const float* in = (z < NB) ? in0 : in1;
    __half* out = (z < NB) ? out0 : out1;
    in  += (size_t)b * C * NTOK;
    out += (size_t)b * NTOK * C;

    const int x0 = blockIdx.x * 32;   // token
    const int y0 = blockIdx.y * 32;   // channel
    const int tx = threadIdx.x & 31, ty = threadIdx.x >> 5;

#pragma unroll
    for (int i = 0; i < 4; i++)
        t[ty + i * 8][tx] = in[(size_t)(y0 + ty + i * 8) * NTOK + x0 + tx];
    __syncthreads();
#pragma unroll
    for (int i = 0; i < 4; i++)
        out[(size_t)(x0 + ty + i * 8) * C + y0 + tx] = __float2half_rn(t[tx][ty + i * 8]);
}

// ---------------------------------------------------------------------------
// Reductions / softmax / stats / combine
// ---------------------------------------------------------------------------
__device__ __forceinline__ float warpMax(float v) {
#pragma unroll
    for (int o = 16; o; o >>= 1) v = fmaxf(v, __shfl_xor_sync(0xffffffffu, v, o));
    return v;
}
__device__ __forceinline__ float warpSum(float v) {
#pragma unroll
    for (int o = 16; o; o >>= 1) v += __shfl_xor_sync(0xffffffffu, v, o);
    return v;
}

// Vectorized masked softmax: float4 S loads, int4 mask loads, uint2 half stores.
// One block per (row n, batch b); 256 threads x 4 float4 chunks = 4096 elems.
__global__ __launch_bounds__(256) void softmax_mask_kernel(
    const float* __restrict__ S, __half* __restrict__ Aout,
    const int* __restrict__ cmask, const int* __restrict__ smask)
{
    const int n = blockIdx.x, b = blockIdx.y;
    const float4* row4 = reinterpret_cast<const float4*>(S + ((size_t)b * NTOK + n) * NTOK);
    uint2* arow = reinterpret_cast<uint2*>(Aout + ((size_t)b * NTOK + n) * NTOK);
    const int4* sm4 = reinterpret_cast<const int4*>(smask + (size_t)b * NTOK);
    const bool cmn = (cmask[(size_t)b * NTOK + n] != 0);
    const int tid = threadIdx.x;
    __shared__ float red[8];

    float4 v[4];
    float mx = -INFINITY;
#pragma unroll
    for (int i = 0; i < 4; i++) {
        const int c = tid + i * 256;
        float4 s = row4[c];
        if (cmn) {
            int4 m = sm4[c];
            if (m.x == 0) s.x = NEGV;
            if (m.y == 0) s.y = NEGV;
            if (m.z == 0) s.z = NEGV;
            if (m.w == 0) s.w = NEGV;
        }
        v[i] = s;
        mx = fmaxf(mx, fmaxf(fmaxf(s.x, s.y), fmaxf(s.z, s.w)));
    }
    mx = warpMax(mx);
    if ((tid & 31) == 0) red[tid >> 5] = mx;
    __syncthreads();
    if (tid < 32) {
        float x = (tid < 8) ? red[tid] : -INFINITY;
        x = warpMax(x);
        if (tid == 0) red[0] = x;
    }
    __syncthreads();
    mx = red[0];
    __syncthreads();

    float sum = 0.f;
#pragma unroll
    for (int i = 0; i < 4; i++) {
        v[i].x = __expf(v[i].x - mx);
        v[i].y = __expf(v[i].y - mx);
        v[i].z = __expf(v[i].z - mx);
        v[i].w = __expf(v[i].w - mx);
        sum += (v[i].x + v[i].y) + (v[i].z + v[i].w);
    }
    sum = warpSum(sum);
    if ((tid & 31) == 0) red[tid >> 5] = sum;
    __syncthreads();
    if (tid < 32) {
        float x = (tid < 8) ? red[tid] : 0.f;
        x = warpSum(x);
        if (tid == 0) red[0] = x;
    }
    __syncthreads();
    const float inv = 1.f / red[0];

#pragma unroll
    for (int i = 0; i < 4; i++) {
        const int c = tid + i * 256;
        __half2 lo = __halves2half2(__float2half_rn(v[i].x * inv), __float2half_rn(v[i].y * inv));
        __half2 hi = __halves2half2(__float2half_rn(v[i].z * inv), __float2half_rn(v[i].w * inv));
        uint2 pk;
        pk.x = *reinterpret_cast<uint32_t*>(&lo);
        pk.y = *reinterpret_cast<uint32_t*>(&hi);
        arow[c] = pk;
    }
}

// Vectorized mvn stats: float4 loads.
__global__ __launch_bounds__(256) void mvn_stats_kernel(
    const float* __restrict__ content,
    float* __restrict__ cmean, float* __restrict__ crstd)
{
    const int c = blockIdx.x, b = blockIdx.y;
    const float4* p4 = reinterpret_cast<const float4*>(content + ((size_t)b * CIN + c) * NTOK);
    const int tid = threadIdx.x;
    float s = 0.f, ss = 0.f;
#pragma unroll
    for (int i = 0; i < 4; i++) {
        float4 x = p4[tid + i * 256];
        s  += (x.x + x.y) + (x.z + x.w);
        ss += (x.x * x.x + x.y * x.y) + (x.z * x.z + x.w * x.w);
    }
    __shared__ float shs[8], shss[8];
    s = warpSum(s); ss = warpSum(ss);
    if ((tid & 31) == 0) { shs[tid >> 5] = s; shss[tid >> 5] = ss; }
    __syncthreads();
    if (tid == 0) {
        float S = 0.f, SS = 0.f;
#pragma unroll
        for (int i = 0; i < 8; i++) { S += shs[i]; SS += shss[i]; }
        float mean = S / (float)NTOK;
        float var = (SS - S * S / (float)NTOK) / (float)(NTOK - 1);
        cmean[b * CIN + c] = mean;
        crstd[b * CIN + c] = rsqrtf(var + EPSV);
    }
}

__global__ __launch_bounds__(256) void combine_kernel(
    const float4* __restrict__ content,
    const float4* __restrict__ meanT,
    const float4* __restrict__ m2T,
    const float* __restrict__ cmean,
    const float* __restrict__ crstd,
    float4* __restrict__ out)
{
    const int gid = blockIdx.x * 256 + threadIdx.x;
    const int bc = gid >> 10;
    const float mu = cmean[bc];
    const float rs = crstd[bc];
    float4 mn = meanT[gid];
    float4 m2 = m2T[gid];
    float4 ct = content[gid];
    float4 o;
    o.x = sqrtf(fmaxf(m2.x - mn.x * mn.x, 0.f)) * ((ct.x - mu) * rs) + mn.x;
    o.y = sqrtf(fmaxf(m2.y - mn.y * mn.y, 0.f)) * ((ct.y - mu) * rs) + mn.y;
    o.z = sqrtf(fmaxf(m2.z - mn.z * mn.z, 0.f)) * ((ct.z - mu) * rs) + mn.z;
    o.w = sqrtf(fmaxf(m2.w - mn.w * mn.w, 0.f)) * ((ct.w - mu) * rs) + mn.w;
    out[gid] = o;
}

// ---------------------------------------------------------------------------
// Launch
// ---------------------------------------------------------------------------
extern "C" void kernel_launch(void* const* d_in, const int* in_sizes, int n_in,
                              void* d_out, int out_size)
{
    const float* content = (const float*)d_in[0];
    const float* style   = (const float*)d_in[1];
    const float* ckey    = (const float*)d_in[2];
    const float* skey    = (const float*)d_in[3];
    const int*   cmask   = (const int*)  d_in[4];
    const int*   smask   = (const int*)  d_in[5];
    const float* Wf = (const float*)d_in[6];
    const float* bf = (const float*)d_in[7];
    const float* Wg = (const float*)d_in[8];
    const float* bg = (const float*)d_in[9];
    const float* Wh = (const float*)d_in[10];
    const float* bh = (const float*)d_in[11];
    float* out = (float*)d_out;

    __half *pckT, *pskT, *pstT, *pFqN, *pGN, *pHv, *pHv2, *pA, *pWf, *pWg, *pWh;
    float *pS, *pMean, *pM2, *pbf, *pbg, *pCm, *pCr;
    cudaGetSymbolAddress((void**)&pckT, g_ckT);
    cudaGetSymbolAddress((void**)&pskT, g_skT);
    cudaGetSymbolAddress((void**)&pstT, g_stT);
    cudaGetSymbolAddress((void**)&pFqN, g_FqN);
    cudaGetSymbolAddress((void**)&pGN,  g_GN);
    cudaGetSymbolAddress((void**)&pHv,  g_HvT);
    cudaGetSymbolAddress((void**)&pHv2, g_Hv2T);
    cudaGetSymbolAddress((void**)&pA,   g_A);
    cudaGetSymbolAddress((void**)&pS,   g_S);
    cudaGetSymbolAddress((void**)&pMean, g_meanT);
    cudaGetSymbolAddress((void**)&pM2,  g_m2T);
    cudaGetSymbolAddress((void**)&pWf,  g_Wf);
    cudaGetSymbolAddress((void**)&pWg,  g_Wg);
    cudaGetSymbolAddress((void**)&pWh,  g_Wh);
    cudaGetSymbolAddress((void**)&pbf,  g_bf);
    cudaGetSymbolAddress((void**)&pbg,  g_bg);
    cudaGetSymbolAddress((void**)&pCm,  g_cmean);
    cudaGetSymbolAddress((void**)&pCr,  g_crstd);

    constexpr int SMEM_STD = (128 * SRS + 128 * SRS) * 2 * NSTG;  // 110592

    static bool attr_done = false;
    if (!attr_done) {
        cudaFuncSetAttribute(mma_gemmH<128, 128, 4, 0, false, float>,
                             cudaFuncAttributeMaxDynamicSharedMemorySize, SMEM_STD);
        cudaFuncSetAttribute(mma_gemmH<128, 128, 4, 2, false, __half>,
                             cudaFuncAttributeMaxDynamicSharedMemorySize, SMEM_STD);
        cudaFuncSetAttribute(mma_gemmH<128, 128, 4, 1, true, __half>,
                             cudaFuncAttributeMaxDynamicSharedMemorySize, SMEM_STD);
        cudaFuncSetAttribute(mma_gemm_dualH,
                             cudaFuncAttributeMaxDynamicSharedMemorySize, DUAL_SMEM);
        attr_done = true;
    }

    const dim3 blk(256);

    // --- weight prep ---
    prep_w_kernel<<<(CKP * CKEY + 255) / 256, blk>>>(Wf, bf, pWf, pbf, CKEY, CKEY, CKP);
    prep_w_kernel<<<(CKP * CKEY + 255) / 256, blk>>>(Wg, bg, pWg, pbg, CKEY, CKEY, CKP);
    prep_w_kernel<<<(CIN * CIN + 255) / 256, blk>>>(Wh, nullptr, pWh, nullptr, CIN, CIN, CIN);

    // --- transpose inputs to token-major half ---
    transpose_in_kernel<CKEY><<<dim3(NTOK / 32, CKEY / 32, 2 * NB), blk>>>(
        ckey, pckT, skey, pskT);
    transpose_in_kernel<CIN><<<dim3(NTOK / 32, CIN / 32, NB), blk>>>(
        style, pstT, style, pstT);

    // --- projections (fp16 mma, fp32 accum), K multiple of 64 ---
    mma_gemmH<128, 128, 4, 2, false, __half><<<dim3(CKP / 128, NTOK / 128, NB), blk, SMEM_STD>>>(
        pckT, pWf, pbf, pFqN, nullptr, CKEY, CKEY, CKEY, CKEY, CKEY,
        (size_t)NTOK * CKEY, 0, (size_t)NTOK * CKEY);
    mma_gemmH<128, 128, 4, 2, false, __half><<<dim3(CKP / 128, NTOK / 128, NB), blk, SMEM_STD>>>(
        pskT, pWg, pbg, pGN, nullptr, CKEY, CKEY, CKEY, CKEY, CKEY,
        (size_t)NTOK * CKEY, 0, (size_t)NTOK * CKEY);
    mma_gemmH<128, 128, 4, 1, true, __half><<<dim3(NTOK / 128, CIN / 128, NB), blk, SMEM_STD>>>(
        pWh, pstT, bh, pHv, pHv2, NTOK, CIN, CIN, CIN, NTOK,
        0, (size_t)NTOK * CIN, (size_t)CIN * NTOK);

    // --- S = FqN @ GN^T (fp32 out) ---
    mma_gemmH<128, 128, 4, 0, false, float><<<dim3(NTOK / 128, NTOK / 128, NB), blk, SMEM_STD>>>(
        pFqN, pGN, nullptr, pS, nullptr, NTOK, CKEY, CKEY, CKEY, NTOK,
        (size_t)NTOK * CKEY, (size_t)NTOK * CKEY, (size_t)NTOK * NTOK);

    // --- masked softmax: fp32 S -> half attn (vectorized) ---
    softmax_mask_kernel<<<dim3(NTOK, NB), blk>>>(pS, pA, cmask, smask);

    // --- fused mean/m2 ---
    mma_gemm_dualH<<<dim3(CIN / 64, NTOK / 128, NB), blk, DUAL_SMEM>>>(
        pA, pHv, pHv2, pMean, pM2);

    // --- mvn stats + final combine ---
    mvn_stats_kernel<<<dim3(CIN, NB), blk>>>(content, pCm, pCr);
    combine_kernel<<<dim3((NB * CIN * NTOK / 4) / 256), blk>>>(
        (const float4*)content, (const float4*)pMean, (const float4*)pM2,
        pCm, pCr, (float4*)out);
}

// round 15
// speedup vs baseline: 1.0208x; 1.0208x over previous
#include <cuda_runtime.h>
#include <cuda_fp16.h>
#include <cstdint>

// ---------------------------------------------------------------------------
// Problem constants
// ---------------------------------------------------------------------------
#define NB   4
#define CIN  256
#define CKEY 448
#define NTOK 4096
#define NEGV (-1e15f)
#define EPSV 1e-5f
#define CKP  512   // padded CKEY for projection N-dim

// ---------------------------------------------------------------------------
// Scratch (static device globals; no runtime allocation)
// ---------------------------------------------------------------------------
__device__ __half g_ckT [(size_t)NB * NTOK * CKEY];   // [b][N][Ck] ckey^T
__device__ __half g_skT [(size_t)NB * NTOK * CKEY];   // [b][N][Ck] skey^T
__device__ __half g_stT [(size_t)NB * NTOK * CIN];    // [b][N][C]  style^T
__device__ __half g_FqN [(size_t)NB * NTOK * CKEY];   // [b][N][Ck] f(ckey)
__device__ __half g_GN  [(size_t)NB * NTOK * CKEY];   // [b][N][Ck] g(skey)
__device__ __half g_HvT [(size_t)NB * CIN  * NTOK];   // [b][C][N]  h(style)
__device__ __half g_Hv2T[(size_t)NB * CIN  * NTOK];   // [b][C][N]  h(style)^2
__device__ float  g_S   [(size_t)NB * NTOK * NTOK];   // [b][N][N]  scores (fp32)
__device__ __half g_A   [(size_t)NB * NTOK * NTOK];   // [b][N][N]  attn (half)
__device__ float  g_meanT[(size_t)NB * CIN * NTOK];   // [b][C][N]
__device__ float  g_m2T [(size_t)NB * CIN  * NTOK];   // [b][C][N]
__device__ __half g_Wf  [CKP * CKEY];                 // rounded, zero-padded rows
__device__ __half g_Wg  [CKP * CKEY];
__device__ __half g_Wh  [CIN * CIN];
__device__ float  g_bf  [CKP];
__device__ float  g_bg  [CKP];
__device__ float  g_cmean[NB * CIN];
__device__ float  g_crstd[NB * CIN];

// ---------------------------------------------------------------------------
// Helpers
// ---------------------------------------------------------------------------
__device__ __forceinline__ uint32_t smem_u32(const void* p) {
    uint32_t a;
    asm("{ .reg .u64 t; cvta.to.shared.u64 t, %1; cvt.u32.u64 %0, t; }"
        : "=r"(a) : "l"(p));
    return a;
}
__device__ __forceinline__ void cp16(uint32_t s, const void* g) {
    asm volatile("cp.async.cg.shared.global [%0], [%1], 16;" :: "r"(s), "l"(g));
}
__device__ __forceinline__ void cp_commit() {
    asm volatile("cp.async.commit_group;" ::: "memory");
}
template <int N> __device__ __forceinline__ void cp_wait() {
    asm volatile("cp.async.wait_group %0;" :: "n"(N) : "memory");
}
__device__ __forceinline__ void mma_f16(float* d, const uint32_t* a, const uint32_t* b) {
    asm volatile(
        "mma.sync.aligned.m16n8k16.row.col.f32.f16.f16.f32 "
        "{%0,%1,%2,%3}, {%4,%5,%6,%7}, {%8,%9}, {%0,%1,%2,%3};"
        : "+f"(d[0]), "+f"(d[1]), "+f"(d[2]), "+f"(d[3])
        : "r"(a[0]), "r"(a[1]), "r"(a[2]), "r"(a[3]), "r"(b[0]), "r"(b[1]));
}
__device__ __forceinline__ void ldsm_x4(uint32_t* r, uint32_t a) {
    asm volatile("ldmatrix.sync.aligned.m8n8.x4.shared.b16 {%0,%1,%2,%3}, [%4];"
        : "=r"(r[0]), "=r"(r[1]), "=r"(r[2]), "=r"(r[3]) : "r"(a));
}

// BK = 64 halves per k-block. smem row stride: 72 halves (144 B).
// LDSM conflict check: chunk index (r*144/16) mod 8 = 9r mod 8 -> 8 distinct.
#define SRS 72
#define NSTG 3   // pipeline stages

// ---------------------------------------------------------------------------
// Generic FP16 mma.sync GEMM:  C[M][N] = A[M][K] * B[N][K]^T   (fp32 accum)
//   256 threads / 2 CTAs per SM, BK=64 halves, 3-stage cp.async pipeline
//   with ONE __syncthreads per iteration, ldmatrix fragment loads.
//   B fragments loaded PAIRED: one ldsm_x4 covers two adjacent 8-row n-blocks
//   (both k-halves), halving B LDSM count.
//   Warp grid WMW x (8/WMW); warp tile (BM/WMW) x (BN*WMW/8). NI must be even.
//   BIAS_MODE: 0 none, 1 along M, 2 along N (bias fp32)
//   SQ: also write C2 = rn(h*h), h = rn(C)  (CT == __half)
//   CT: output type (float or __half). Store guard: col < Nrt.
//   K must be a multiple of 64.
// ---------------------------------------------------------------------------
template <int BM, int BN, int WMW, int BIAS_MODE, bool SQ, typename CT>
__global__ __launch_bounds__(256, 2) void mma_gemmH(
    const __half* __restrict__ A, const __half* __restrict__ B,
    const float* __restrict__ bias,
    CT* __restrict__ C, CT* __restrict__ C2,
    int Nrt, int K, int lda, int ldb, int ldc,
    size_t sA, size_t sB, size_t sC)
{
    constexpr int WNW = 8 / WMW;
    constexpr int WTM = BM / WMW;
    constexpr int WTN = BN / WNW;
    constexpr int MI  = WTM / 16;
    constexpr int NI  = WTN / 8;
    static_assert(NI % 2 == 0, "NI must be even for paired B ldsm_x4");
    constexpr int ASZ = BM * SRS;          // halves
    constexpr int BSZ = BN * SRS;
    constexpr int STG = ASZ + BSZ;
    constexpr int ACH = BM * 8 / 256;      // cp16 chunks per thread (A), 8 per row
    constexpr int BCH = BN * 8 / 256;

    extern __shared__ __half smh[];
    const uint32_t sbase = smem_u32(smh);

    const int tid = threadIdx.x, lane = tid & 31, wid = tid >> 5;
    const int wM = wid % WMW, wN = wid / WMW;
    const int m0 = blockIdx.y * BM, n0 = blockIdx.x * BN, b = blockIdx.z;

    A += (size_t)b * sA + (size_t)m0 * lda;
    B += (size_t)b * sB + (size_t)n0 * ldb;
    C += (size_t)b * sC;
    if (SQ) C2 += (size_t)b * sC;

    float acc[MI][NI][4];
#pragma unroll
    for (int mi = 0; mi < MI; mi++)
#pragma unroll
        for (int ni = 0; ni < NI; ni++)
#pragma unroll
            for (int q = 0; q < 4; q++) acc[mi][ni][q] = 0.f;

    const int NK = K >> 6;   // 64 halves per k-block

    // prefetch stages 0 and 1
#pragma unroll
    for (int p = 0; p < 2; p++) {
        if (p < NK) {
            const uint32_t sb = sbase + (uint32_t)(p * STG) * 2;
            const int k0 = p << 6;
#pragma unroll
            for (int v = 0; v < ACH; v++) {
                int t = tid + v * 256, r = t >> 3, ch = t & 7;
                cp16(sb + (uint32_t)(r * SRS + ch * 8) * 2, A + (size_t)r * lda + k0 + ch * 8);
            }
#pragma unroll
            for (int v = 0; v < BCH; v++) {
                int t = tid + v * 256, r = t >> 3, ch = t & 7;
                cp16(sb + (uint32_t)(ASZ + r * SRS + ch * 8) * 2, B + (size_t)r * ldb + k0 + ch * 8);
            }
        }
        cp_commit();
    }

    const int g = lane >> 2, tq = lane & 3;
    // ldmatrix per-lane offsets (bytes)
    // A x4: 16 rows, 2 k-halves
    const uint32_t aoff = (uint32_t)((lane & 15) * SRS + (lane >> 4) * 8) * 2;
    // B paired x4: rows (lane&7) + ((lane>>4)&1)*8, k-half ((lane>>3)&1)*8
    const uint32_t boff4 = (uint32_t)(((lane & 7) + ((lane >> 4) & 1) * 8) * SRS
                                      + ((lane >> 3) & 1) * 8) * 2;

    int stg = 0, pstg = 2;
    for (int i = 0; i < NK; i++) {
        cp_wait<1>();
        __syncthreads();

        if (i + 2 < NK) {
            const uint32_t sb = sbase + (uint32_t)(pstg * STG) * 2;
            const int k0 = (i + 2) << 6;
#pragma unroll
            for (int v = 0; v < ACH; v++) {
                int t = tid + v * 256, r = t >> 3, ch = t & 7;
                cp16(sb + (uint32_t)(r * SRS + ch * 8) * 2, A + (size_t)r * lda + k0 + ch * 8);
            }
#pragma unroll
            for (int v = 0; v < BCH; v++) {
                int t = tid + v * 256, r = t >> 3, ch = t & 7;
                cp16(sb + (uint32_t)(ASZ + r * SRS + ch * 8) * 2, B + (size_t)r * ldb + k0 + ch * 8);
            }
        }
        cp_commit();
        if (++pstg == NSTG) pstg = 0;

        const uint32_t stg_b = sbase + (uint32_t)(stg * STG) * 2;
        const uint32_t bstg_b = stg_b + (uint32_t)ASZ * 2;

#pragma unroll
        for (int kk = 0; kk < 4; kk++) {
            const uint32_t kh = kk * 16 * 2;   // byte offset within row
            uint32_t af[MI][4], bf[NI][2];
#pragma unroll
            for (int mi = 0; mi < MI; mi++)
                ldsm_x4(af[mi], stg_b + (uint32_t)((wM * WTM + mi * 16) * SRS) * 2 + kh + aoff);
#pragma unroll
            for (int np = 0; np < NI / 2; np++) {
                uint32_t b4[4];
                ldsm_x4(b4, bstg_b + (uint32_t)((wN * WTN + np * 16) * SRS) * 2 + kh + boff4);
                bf[np * 2][0] = b4[0];     bf[np * 2][1] = b4[1];
                bf[np * 2 + 1][0] = b4[2]; bf[np * 2 + 1][1] = b4[3];
            }
#pragma unroll
            for (int mi = 0; mi < MI; mi++)
#pragma unroll
                for (int ni = 0; ni < NI; ni++)
                    mma_f16(acc[mi][ni], af[mi], bf[ni]);
        }
        if (++stg == NSTG) stg = 0;
    }

    // ---- epilogue ----
#pragma unroll
    for (int mi = 0; mi < MI; mi++) {
        const int row0 = m0 + wM * WTM + mi * 16 + g;
        float bm0 = 0.f, bm1 = 0.f;
        if (BIAS_MODE == 1) { bm0 = bias[row0]; bm1 = bias[row0 + 8]; }
#pragma unroll
        for (int ni = 0; ni < NI; ni++) {
            const int col = n0 + wN * WTN + ni * 8 + tq * 2;
            if (col >= Nrt) continue;
            float o0 = acc[mi][ni][0], o1 = acc[mi][ni][1];
            float o2 = acc[mi][ni][2], o3 = acc[mi][ni][3];
            if (BIAS_MODE == 1) { o0 += bm0; o1 += bm0; o2 += bm1; o3 += bm1; }
            if (BIAS_MODE == 2) {
                float bn0 = bias[col], bn1 = bias[col + 1];
                o0 += bn0; o1 += bn1; o2 += bn0; o3 += bn1;
            }
            if (sizeof(CT) == 4) {
                float* Cf = reinterpret_cast<float*>(C);
                *reinterpret_cast<float2*>(&Cf[(size_t)row0 * ldc + col])       = make_float2(o0, o1);
                *reinterpret_cast<float2*>(&Cf[(size_t)(row0 + 8) * ldc + col]) = make_float2(o2, o3);
            } else {
                __half* Ch = reinterpret_cast<__half*>(C);
                __half h0 = __float2half_rn(o0), h1 = __float2half_rn(o1);
                __half h2 = __float2half_rn(o2), h3 = __float2half_rn(o3);
                *reinterpret_cast<__half2*>(&Ch[(size_t)row0 * ldc + col])       = __halves2half2(h0, h1);
                *reinterpret_cast<__half2*>(&Ch[(size_t)(row0 + 8) * ldc + col]) = __halves2half2(h2, h3);
                if (SQ) {
                    __half* C2h = reinterpret_cast<__half*>(C2);
                    float f0 = __half2float(h0), f1 = __half2float(h1);
                    float f2 = __half2float(h2), f3 = __half2float(h3);
                    __half q0 = __float2half_rn(f0 * f0), q1 = __float2half_rn(f1 * f1);
                    __half q2 = __float2half_rn(f2 * f2), q3 = __float2half_rn(f3 * f3);
                    *reinterpret_cast<__half2*>(&C2h[(size_t)row0 * ldc + col])       = __halves2half2(q0, q1);
                    *reinterpret_cast<__half2*>(&C2h[(size_t)(row0 + 8) * ldc + col]) = __halves2half2(q2, q3);
                }
            }
        }
    }
}

// ---------------------------------------------------------------------------
// Dual-B fused FP16 GEMM for mean & m2 (shares attn A tiles), BK=64, 3-stage:
//   C1[n][c] = A[n][:] . B1[c][:],  C2[n][c] = A[n][:] . B2[c][:]
//   BM=128 (tokens), BN=64 (channels), warps 4x2 -> warp tile 32x32.
//   2 CTAs/SM. fp32 accumulate. Paired ldsm_x4 B loads.
//   Epilogue: smem-staged transpose -> coalesced float4 stores of out[c][n].
// ---------------------------------------------------------------------------
#define DUAL_SMEM ((128 * SRS + 2 * 64 * SRS) * 2 * NSTG)
#define TPD 132   // transpose tile row stride (floats)
__global__ __launch_bounds__(256, 2) void mma_gemm_dualH(
    const __half* __restrict__ A, const __half* __restrict__ B1,
    const __half* __restrict__ B2,
    float* __restrict__ C1, float* __restrict__ C2)
{
    constexpr int BM = 128, BN = 64;
    constexpr int ASZ = BM * SRS, BSZ = BN * SRS;
    constexpr int STG = ASZ + 2 * BSZ;

    extern __shared__ __half smh[];
    const uint32_t sbase = smem_u32(smh);

    const int tid = threadIdx.x, lane = tid & 31, wid = tid >> 5;
    const int wM = wid & 3, wN = wid >> 2;
    const int m0 = blockIdx.y * BM, n0 = blockIdx.x * BN, b = blockIdx.z;

    A  += (size_t)b * NTOK * NTOK + (size_t)m0 * NTOK;
    B1 += (size_t)b * CIN * NTOK + (size_t)n0 * NTOK;
    B2 += (size_t)b * CIN * NTOK + (size_t)n0 * NTOK;
    C1 += (size_t)b * CIN * NTOK;
    C2 += (size_t)b * CIN * NTOK;

    float acc1[2][4][4], acc2[2][4][4];
#pragma unroll
    for (int mi = 0; mi < 2; mi++)
#pragma unroll
        for (int ni = 0; ni < 4; ni++)
#pragma unroll
            for (int q = 0; q < 4; q++) { acc1[mi][ni][q] = 0.f; acc2[mi][ni][q] = 0.f; }

    const int NK = NTOK >> 6;   // 64

    // prefetch stages 0, 1
#pragma unroll
    for (int p = 0; p < 2; p++) {
        const uint32_t sb = sbase + (uint32_t)(p * STG) * 2;
        const int k0 = p << 6;
#pragma unroll
        for (int v = 0; v < 4; v++) {
            int t = tid + v * 256, r = t >> 3, ch = t & 7;
            cp16(sb + (uint32_t)(r * SRS + ch * 8) * 2, A + (size_t)r * NTOK + k0 + ch * 8);
        }
#pragma unroll
        for (int v = 0; v < 2; v++) {
            int t = tid + v * 256, r = t >> 3, ch = t & 7;
            cp16(sb + (uint32_t)(ASZ + r * SRS + ch * 8) * 2, B1 + (size_t)r * NTOK + k0 + ch * 8);
            cp16(sb + (uint32_t)(ASZ + BSZ + r * SRS + ch * 8) * 2, B2 + (size_t)r * NTOK + k0 + ch * 8);
        }
        cp_commit();
    }

    const int g = lane >> 2, tq = lane & 3;
    const uint32_t aoff = (uint32_t)((lane & 15) * SRS + (lane >> 4) * 8) * 2;
    const uint32_t boff4 = (uint32_t)(((lane & 7) + ((lane >> 4) & 1) * 8) * SRS
                                      + ((lane >> 3) & 1) * 8) * 2;

    int stg = 0, pstg = 2;
    for (int i = 0; i < NK; i++) {
        cp_wait<1>();
        __syncthreads();

        if (i + 2 < NK) {
            const uint32_t sb = sbase + (uint32_t)(pstg * STG) * 2;
            const int k0 = (i + 2) << 6;
#pragma unroll
            for (int v = 0; v < 4; v++) {
                int t = tid + v * 256, r = t >> 3, ch = t & 7;
                cp16(sb + (uint32_t)(r * SRS + ch * 8) * 2, A + (size_t)r * NTOK + k0 + ch * 8);
            }
#pragma unroll
            for (int v = 0; v < 2; v++) {
                int t = tid + v * 256, r = t >> 3, ch = t & 7;
                cp16(sb + (uint32_t)(ASZ + r * SRS + ch * 8) * 2, B1 + (size_t)r * NTOK + k0 + ch * 8);
                cp16(sb + (uint32_t)(ASZ + BSZ + r * SRS + ch * 8) * 2, B2 + (size_t)r * NTOK + k0 + ch * 8);
            }
        }
        cp_commit();
        if (++pstg == NSTG) pstg = 0;

        const uint32_t stg_b = sbase + (uint32_t)(stg * STG) * 2;
        const uint32_t b1stg = stg_b + (uint32_t)ASZ * 2;
        const uint32_t b2stg = b1stg + (uint32_t)BSZ * 2;

#pragma unroll
        for (int kk = 0; kk < 4; kk++) {
            const uint32_t kh = kk * 16 * 2;
            uint32_t af[2][4], bf1[4][2], bf2[4][2];
#pragma unroll
            for (int mi = 0; mi < 2; mi++)
                ldsm_x4(af[mi], stg_b + (uint32_t)((wM * 32 + mi * 16) * SRS) * 2 + kh + aoff);
#pragma unroll
            for (int np = 0; np < 2; np++) {
                uint32_t b4[4];
                ldsm_x4(b4, b1stg + (uint32_t)((wN * 32 + np * 16) * SRS) * 2 + kh + boff4);
                bf1[np * 2][0] = b4[0];     bf1[np * 2][1] = b4[1];
                bf1[np * 2 + 1][0] = b4[2]; bf1[np * 2 + 1][1] = b4[3];
                ldsm_x4(b4, b2stg + (uint32_t)((wN * 32 + np * 16) * SRS) * 2 + kh + boff4);
                bf2[np * 2][0] = b4[0];     bf2[np * 2][1] = b4[1];
                bf2[np * 2 + 1][0] = b4[2]; bf2[np * 2 + 1][1] = b4[3];
            }
#pragma unroll
            for (int mi = 0; mi < 2; mi++)
#pragma unroll
                for (int ni = 0; ni < 4; ni++) {
                    mma_f16(acc1[mi][ni], af[mi], bf1[ni]);
                    mma_f16(acc2[mi][ni], af[mi], bf2[ni]);
                }
        }
        if (++stg == NSTG) stg = 0;
    }

    // ---- epilogue: smem transpose -> coalesced float4 row stores ----
    __syncthreads();   // mainloop smem dead; safe to reuse
    float* smt = reinterpret_cast<float*>(smh);   // [BN][TPD]

#pragma unroll
    for (int pass = 0; pass < 2; pass++) {
        float (*acc)[4][4] = (pass == 0) ? acc1 : acc2;
        float* Cout = (pass == 0) ? C1 : C2;
#pragma unroll
        for (int mi = 0; mi < 2; mi++) {
            const int row = wM * 32 + mi * 16 + g;      // local token row
#pragma unroll
            for (int ni = 0; ni < 4; ni++) {
                const int col = wN * 32 + ni * 8 + tq * 2;  // local channel
                smt[col * TPD + row]           = acc[mi][ni][0];
                smt[(col + 1) * TPD + row]     = acc[mi][ni][1];
                smt[col * TPD + row + 8]       = acc[mi][ni][2];
                smt[(col + 1) * TPD + row + 8] = acc[mi][ni][3];
            }
        }
        __syncthreads();
#pragma unroll
        for (int v = 0; v < 8; v++) {
            int idx = tid + v * 256;        // 2048 float4 chunks
            int col = idx >> 5, ch = idx & 31;
            float4 val = *reinterpret_cast<float4*>(&smt[col * TPD + ch * 4]);
            *reinterpret_cast<float4*>(&Cout[(size_t)(n0 + col) * NTOK + m0 + ch * 4]) = val;
        }
        __syncthreads();
    }
}

// ---------------------------------------------------------------------------
// Weight prep: round W to half, pad rows to dstRows with zeros; pad bias (f32).
// ---------------------------------------------------------------------------
__global__ void prep_w_kernel(const float* __restrict__ W, const float* __restrict__ bias,
                              __half* __restrict__ Wd, float* __restrict__ bd,
                              int rows, int cols, int dstRows)
{
    int i = blockIdx.x * 256 + threadIdx.x;
    int total = dstRows * cols;
    if (i < total) {
        int r = i / cols;
        Wd[i] = (r < rows) ? __float2half_rn(W[i]) : __float2half_rn(0.f);
    }
    if (bd && i < dstRows) bd[i] = (i < rows) ? bias[i] : 0.f;
}

// ---------------------------------------------------------------------------
// Transpose [C][N] fp32 -> [N][C] half. Two tensors via z split.
// ---------------------------------------------------------------------------
template <int C>
__global__ __launch_bounds__(256) void transpose_in_kernel(
    const float* __restrict__ in0, __half* __restrict__ out0,
    const float* __restrict__ in1, __half* __restrict__ out1)
{
    __shared__ float t[32][33];
    const int z = blockIdx.z;
    const int b = z & (NB - 1);
    const float* in = (z < NB) ? in0 : in1;
    __half* out = (z < NB) ? out0 : out1;
    in  += (size_t)b * C * NTOK;
    out += (size_t)b * NTOK * C;

    const int x0 = blockIdx.x * 32;   // token
    const int y0 = blockIdx.y * 32;   // channel
    const int tx = threadIdx.x & 31, ty = threadIdx.x >> 5;

#pragma unroll
    for (int i = 0; i < 4; i++)
        t[ty + i * 8][tx] = in[(size_t)(y0 + ty + i * 8) * NTOK + x0 + tx];
    __syncthreads();
#pragma unroll
    for (int i = 0; i < 4; i++)
        out[(size_t)(x0 + ty + i * 8) * C + y0 + tx] = __float2half_rn(t[tx][ty + i * 8]);
}

// ---------------------------------------------------------------------------
// Reductions / softmax / stats / combine
// ---------------------------------------------------------------------------
__device__ __forceinline__ float warpMax(float v) {
#pragma unroll
    for (int o = 16; o; o >>= 1) v = fmaxf(v, __shfl_xor_sync(0xffffffffu, v, o));
    return v;
}
__device__ __forceinline__ float warpSum(float v) {
#pragma unroll
    for (int o = 16; o; o >>= 1) v += __shfl_xor_sync(0xffffffffu, v, o);
    return v;
}

// Vectorized masked softmax: float4 S loads, int4 mask loads, uint2 half stores.
__global__ __launch_bounds__(256) void softmax_mask_kernel(
    const float* __restrict__ S, __half* __restrict__ Aout,
    const int* __restrict__ cmask, const int* __restrict__ smask)
{
    const int n = blockIdx.x, b = blockIdx.y;
    const float4* row4 = reinterpret_cast<const float4*>(S + ((size_t)b * NTOK + n) * NTOK);
    uint2* arow = reinterpret_cast<uint2*>(Aout + ((size_t)b * NTOK + n) * NTOK);
    const int4* sm4 = reinterpret_cast<const int4*>(smask + (size_t)b * NTOK);
    const bool cmn = (cmask[(size_t)b * NTOK + n] != 0);
    const int tid = threadIdx.x;
    __shared__ float red[8];

    float4 v[4];
    float mx = -INFINITY;
#pragma unroll
    for (int i = 0; i < 4; i++) {
        const int c = tid + i * 256;
        float4 s = row4[c];
        if (cmn) {
            int4 m = sm4[c];
            if (m.x == 0) s.x = NEGV;
            if (m.y == 0) s.y = NEGV;
            if (m.z == 0) s.z = NEGV;
            if (m.w == 0) s.w = NEGV;
        }
        v[i] = s;
        mx = fmaxf(mx, fmaxf(fmaxf(s.x, s.y), fmaxf(s.z, s.w)));
    }
    mx = warpMax(mx);
    if ((tid & 31) == 0) red[tid >> 5] = mx;
    __syncthreads();
    if (tid < 32) {
        float x = (tid < 8) ? red[tid] : -INFINITY;
        x = warpMax(x);
        if (tid == 0) red[0] = x;
    }
    __syncthreads();
    mx = red[0];
    __syncthreads();

    float sum = 0.f;
#pragma unroll
    for (int i = 0; i < 4; i++) {
        v[i].x = __expf(v[i].x - mx);
        v[i].y = __expf(v[i].y - mx);
        v[i].z = __expf(v[i].z - mx);
        v[i].w = __expf(v[i].w - mx);
        sum += (v[i].x + v[i].y) + (v[i].z + v[i].w);
    }
    sum = warpSum(sum);
    if ((tid & 31) == 0) red[tid >> 5] = sum;
    __syncthreads();
    if (tid < 32) {
        float x = (tid < 8) ? red[tid] : 0.f;
        x = warpSum(x);
        if (tid == 0) red[0] = x;
    }
    __syncthreads();
    const float inv = 1.f / red[0];

#pragma unroll
    for (int i = 0; i < 4; i++) {
        const int c = tid + i * 256;
        __half2 lo = __halves2half2(__float2half_rn(v[i].x * inv), __float2half_rn(v[i].y * inv));
        __half2 hi = __halves2half2(__float2half_rn(v[i].z * inv), __float2half_rn(v[i].w * inv));
        uint2 pk;
        pk.x = *reinterpret_cast<uint32_t*>(&lo);
        pk.y = *reinterpret_cast<uint32_t*>(&hi);
        arow[c] = pk;
    }
}

// Vectorized mvn stats: float4 loads.
__global__ __launch_bounds__(256) void mvn_stats_kernel(
    const float* __restrict__ content,
    float* __restrict__ cmean, float* __restrict__ crstd)
{
    const int c = blockIdx.x, b = blockIdx.y;
    const float4* p4 = reinterpret_cast<const float4*>(content + ((size_t)b * CIN + c) * NTOK);
    const int tid = threadIdx.x;
    float s = 0.f, ss = 0.f;
#pragma unroll
    for (int i = 0; i < 4; i++) {
        float4 x = p4[tid + i * 256];
        s  += (x.x + x.y) + (x.z + x.w);
        ss += (x.x * x.x + x.y * x.y) + (x.z * x.z + x.w * x.w);
    }
    __shared__ float shs[8], shss[8];
    s = warpSum(s); ss = warpSum(ss);
    if ((tid & 31) == 0) { shs[tid >> 5] = s; shss[tid >> 5] = ss; }
    __syncthreads();
    if (tid == 0) {
        float S = 0.f, SS = 0.f;
#pragma unroll
        for (int i = 0; i < 8; i++) { S += shs[i]; SS += shss[i]; }
        float mean = S / (float)NTOK;
        float var = (SS - S * S / (float)NTOK) / (float)(NTOK - 1);
        cmean[b * CIN + c] = mean;
        crstd[b * CIN + c] = rsqrtf(var + EPSV);
    }
}

__global__ __launch_bounds__(256) void combine_kernel(
    const float4* __restrict__ content,
    const float4* __restrict__ meanT,
    const float4* __restrict__ m2T,
    const float* __restrict__ cmean,
    const float* __restrict__ crstd,
    float4* __restrict__ out)
{
    const int gid = blockIdx.x * 256 + threadIdx.x;
    const int bc = gid >> 10;
    const float mu = cmean[bc];
    const float rs = crstd[bc];
    float4 mn = meanT[gid];
    float4 m2 = m2T[gid];
    float4 ct = content[gid];
    float4 o;
    o.x = sqrtf(fmaxf(m2.x - mn.x * mn.x, 0.f)) * ((ct.x - mu) * rs) + mn.x;
    o.y = sqrtf(fmaxf(m2.y - mn.y * mn.y, 0.f)) * ((ct.y - mu) * rs) + mn.y;
    o.z = sqrtf(fmaxf(m2.z - mn.z * mn.z, 0.f)) * ((ct.z - mu) * rs) + mn.z;
    o.w = sqrtf(fmaxf(m2.w - mn.w * mn.w, 0.f)) * ((ct.w - mu) * rs) + mn.w;
    out[gid] = o;
}

// ---------------------------------------------------------------------------
// Launch
// ---------------------------------------------------------------------------
extern "C" void kernel_launch(void* const* d_in, const int* in_sizes, int n_in,
                              void* d_out, int out_size)
{
    const float* content = (const float*)d_in[0];
    const float* style   = (const float*)d_in[1];
    const float* ckey    = (const float*)d_in[2];
    const float* skey    = (const float*)d_in[3];
    const int*   cmask   = (const int*)  d_in[4];
    const int*   smask   = (const int*)  d_in[5];
    const float* Wf = (const float*)d_in[6];
    const float* bf = (const float*)d_in[7];
    const float* Wg = (const float*)d_in[8];
    const float* bg = (const float*)d_in[9];
    const float* Wh = (const float*)d_in[10];
    const float* bh = (const float*)d_in[11];
    float* out = (float*)d_out;

    __half *pckT, *pskT, *pstT, *pFqN, *pGN, *pHv, *pHv2, *pA, *pWf, *pWg, *pWh;
    float *pS, *pMean, *pM2, *pbf, *pbg, *pCm, *pCr;
    cudaGetSymbolAddress((void**)&pckT, g_ckT);
    cudaGetSymbolAddress((void**)&pskT, g_skT);
    cudaGetSymbolAddress((void**)&pstT, g_stT);
    cudaGetSymbolAddress((void**)&pFqN, g_FqN);
    cudaGetSymbolAddress((void**)&pGN,  g_GN);
    cudaGetSymbolAddress((void**)&pHv,  g_HvT);
    cudaGetSymbolAddress((void**)&pHv2, g_Hv2T);
    cudaGetSymbolAddress((void**)&pA,   g_A);
    cudaGetSymbolAddress((void**)&pS,   g_S);
    cudaGetSymbolAddress((void**)&pMean, g_meanT);
    cudaGetSymbolAddress((void**)&pM2,  g_m2T);
    cudaGetSymbolAddress((void**)&pWf,  g_Wf);
    cudaGetSymbolAddress((void**)&pWg,  g_Wg);
    cudaGetSymbolAddress((void**)&pWh,  g_Wh);
    cudaGetSymbolAddress((void**)&pbf,  g_bf);
    cudaGetSymbolAddress((void**)&pbg,  g_bg);
    cudaGetSymbolAddress((void**)&pCm,  g_cmean);
    cudaGetSymbolAddress((void**)&pCr,  g_crstd);

    constexpr int SMEM_STD = (128 * SRS + 128 * SRS) * 2 * NSTG;  // 110592

    static bool attr_done = false;
    if (!attr_done) {
        cudaFuncSetAttribute(mma_gemmH<128, 128, 4, 0, false, float>,
                             cudaFuncAttributeMaxDynamicSharedMemorySize, SMEM_STD);
        cudaFuncSetAttribute(mma_gemmH<128, 128, 4, 2, false, __half>,
                             cudaFuncAttributeMaxDynamicSharedMemorySize, SMEM_STD);
        cudaFuncSetAttribute(mma_gemmH<128, 128, 4, 1, true, __half>,
                             cudaFuncAttributeMaxDynamicSharedMemorySize, SMEM_STD);
        cudaFuncSetAttribute(mma_gemm_dualH,
                             cudaFuncAttributeMaxDynamicSharedMemorySize, DUAL_SMEM);
        attr_done = true;
    }

    const dim3 blk(256);

    // --- weight prep ---
    prep_w_kernel<<<(CKP * CKEY + 255) / 256, blk>>>(Wf, bf, pWf, pbf, CKEY, CKEY, CKP);
    prep_w_kernel<<<(CKP * CKEY + 255) / 256, blk>>>(Wg, bg, pWg, pbg, CKEY, CKEY, CKP);
    prep_w_kernel<<<(CIN * CIN + 255) / 256, blk>>>(Wh, nullptr, pWh, nullptr, CIN, CIN, CIN);

    // --- transpose inputs to token-major half ---
    transpose_in_kernel<CKEY><<<dim3(NTOK / 32, CKEY / 32, 2 * NB), blk>>>(
        ckey, pckT, skey, pskT);
    transpose_in_kernel<CIN><<<dim3(NTOK / 32, CIN / 32, NB), blk>>>(
        style, pstT, style, pstT);

    // --- projections (fp16 mma, fp32 accum), K multiple of 64 ---
    mma_gemmH<128, 128, 4, 2, false, __half><<<dim3(CKP / 128, NTOK / 128, NB), blk, SMEM_STD>>>(
        pckT, pWf, pbf, pFqN, nullptr, CKEY, CKEY, CKEY, CKEY, CKEY,
        (size_t)NTOK * CKEY, 0, (size_t)NTOK * CKEY);
    mma_gemmH<128, 128, 4, 2, false, __half><<<dim3(CKP / 128, NTOK / 128, NB), blk, SMEM_STD>>>(
        pskT, pWg, pbg, pGN, nullptr, CKEY, CKEY, CKEY, CKEY, CKEY,
        (size_t)NTOK * CKEY, 0, (size_t)NTOK * CKEY);
    mma_gemmH<128, 128, 4, 1, true, __half><<<dim3(NTOK / 128, CIN / 128, NB), blk, SMEM_STD>>>(
        pWh, pstT, bh, pHv, pHv2, NTOK, CIN, CIN, CIN, NTOK,
        0, (size_t)NTOK * CIN, (size_t)CIN * NTOK);

    // --- S = FqN @ GN^T (fp32 out) ---
    mma_gemmH<128, 128, 4, 0, false, float><<<dim3(NTOK / 128, NTOK / 128, NB), blk, SMEM_STD>>>(
        pFqN, pGN, nullptr, pS, nullptr, NTOK, CKEY, CKEY, CKEY, NTOK,
        (size_t)NTOK * CKEY, (size_t)NTOK * CKEY, (size_t)NTOK * NTOK);

    // --- masked softmax: fp32 S -> half attn (vectorized) ---
    softmax_mask_kernel<<<dim3(NTOK, NB), blk>>>(pS, pA, cmask, smask);

    // --- fused mean/m2 ---
    mma_gemm_dualH<<<dim3(CIN / 64, NTOK / 128, NB), blk, DUAL_SMEM>>>(
        pA, pHv, pHv2, pMean, pM2);

    // --- mvn stats + final combine ---
    mvn_stats_kernel<<<dim3(CIN, NB), blk>>>(content, pCm, pCr);
    combine_kernel<<<dim3((NB * CIN * NTOK / 4) / 256), blk>>>(
        (const float4*)content, (const float4*)pMean, (const float4*)pM2,
        pCm, pCr, (float4*)out);
}